// round 7
// baseline (speedup 1.0000x reference)
#include <cuda_runtime.h>
#include <cuda_fp16.h>
#include <cstdint>

// ---------------- problem constants ----------------
#define IN_F   4096
#define OUT_F  16384
#define NTOK   64
#define RANK   64

#define BLOCK_M 128          // out-features per CTA
#define KBLK    32           // K elems per pipeline stage
#define XSTAGES 4
#define NCHUNK_MAIN (IN_F / KBLK)             // 128
#define NCHUNK_TOT  (NCHUNK_MAIN + RANK/KBLK) // 130

// ---------------- SMEM layout (40 KB total) ----------------
#define PH         40                          // fp16 row pitch (halfs)
#define WH_BYTES   (BLOCK_M * PH * 2)          // 10240 B per buffer
#define OFF_WH     0                           // x2 buffers
#define OFF_XH     (2 * WH_BYTES)              // 20480
#define XH_STAGE_B (NTOK * PH * 2)             // 5120 B
#define SMEM_BYTES (OFF_XH + XSTAGES * XH_STAGE_B)  // 40960

// device scratch
__device__ __align__(256) __half g_xh[NTOK * IN_F];   // x in fp16
__device__ __align__(256) __half g_t2h[NTOK * RANK];  // 2*(x@A^T) in fp16

// ---------------- PTX helpers ----------------
__device__ __forceinline__ uint32_t smem_u32(const void* p) {
    uint32_t a;
    asm("{ .reg .u64 t; cvta.to.shared.u64 t, %1; cvt.u32.u64 %0, t; }" : "=r"(a) : "l"(p));
    return a;
}
__device__ __forceinline__ void cp16(uint32_t dst, const void* src) {
    asm volatile("cp.async.cg.shared.global [%0], [%1], 16;" :: "r"(dst), "l"(src));
}
#define CP_COMMIT() asm volatile("cp.async.commit_group;" ::: "memory")
#define CP_WAIT2()  asm volatile("cp.async.wait_group 2;" ::: "memory")

__device__ __forceinline__ void ldsm4(uint32_t* r, uint32_t addr) {
    asm volatile("ldmatrix.sync.aligned.m8n8.x4.shared.b16 {%0,%1,%2,%3}, [%4];"
                 : "=r"(r[0]), "=r"(r[1]), "=r"(r[2]), "=r"(r[3]) : "r"(addr));
}
__device__ __forceinline__ void mma_f16(float* d, const uint32_t* a,
                                        uint32_t b0, uint32_t b1) {
    asm volatile(
        "mma.sync.aligned.m16n8k16.row.col.f32.f16.f16.f32 "
        "{%0,%1,%2,%3}, {%4,%5,%6,%7}, {%8,%9}, {%0,%1,%2,%3};"
        : "+f"(d[0]), "+f"(d[1]), "+f"(d[2]), "+f"(d[3])
        : "r"(a[0]), "r"(a[1]), "r"(a[2]), "r"(a[3]), "r"(b0), "r"(b1));
}
__device__ __forceinline__ uint32_t h2u(__half2 h) {
    return *reinterpret_cast<uint32_t*>(&h);
}

// ---------------- prep 1: x -> fp16 ----------------
__global__ void __launch_bounds__(256) x2h_kernel(const float4* __restrict__ x4,
                                                  uint2* __restrict__ xh2) {
    int i = blockIdx.x * 256 + threadIdx.x;
    float4 v = x4[i];
    uint2 o;
    o.x = h2u(__floats2half2_rn(v.x, v.y));
    o.y = h2u(__floats2half2_rn(v.z, v.w));
    xh2[i] = o;
}

// ---------------- prep 2: t2h = fp16( 2 * (x @ A^T) ) ----------------
__global__ void __launch_bounds__(256) lora_t_kernel(const float* __restrict__ x,
                                                     const float* __restrict__ A,
                                                     __half* __restrict__ t2) {
    __shared__ float red[256];
    int tid  = threadIdx.x;
    int pair = tid & 63;
    int i  = pair >> 3;
    int j  = pair & 7;
    int kg = tid >> 6;
    int gi = (blockIdx.x >> 3) * 8 + i;
    int gj = (blockIdx.x & 7) * 8 + j;

    const float4* xr = (const float4*)(x + (size_t)gi * IN_F);
    const float4* ar = (const float4*)(A + (size_t)gj * IN_F);
    float acc = 0.f;
    int k0 = kg * 256;
#pragma unroll 4
    for (int k = k0; k < k0 + 256; ++k) {
        float4 a = xr[k];
        float4 b = ar[k];
        acc += a.x * b.x + a.y * b.y + a.z * b.z + a.w * b.w;
    }
    red[tid] = acc;
    __syncthreads();
    if (kg == 0) {
        float s = red[pair] + red[pair + 64] + red[pair + 128] + red[pair + 192];
        t2[gi * RANK + gj] = __float2half_rn(2.0f * s);
    }
}

// ---------------- main fused GEMM ----------------
// 128 CTAs, 256 threads (8 warps: 4 along M x 2 along N).
// W: gmem fp32 -> registers (LDG, double buffer, distance 2) -> cvt -> STS fp16.
// X: 4-deep cp.async ring. ONE __syncthreads per iteration.
__global__ void __launch_bounds__(256, 1) lora_main_kernel(
    const __half* __restrict__ xh,     // [64,4096] fp16
    const float*  __restrict__ w,      // [16384,4096] fp32
    const float*  __restrict__ lB,     // [16384,64] fp32
    const __half* __restrict__ t2h,    // [64,64] fp16 (incl. 2x scale)
    float* __restrict__ out)           // [64,16384]
{
    extern __shared__ __align__(16) char smem_c[];
    const uint32_t sb = smem_u32(smem_c);
    const int tid  = threadIdx.x;
    const int wid  = tid >> 5;
    const int lane = tid & 31;
    const int g = lane >> 2;
    const int t = lane & 3;
    const int wm = (wid & 3) * 32;    // warp M offset
    const int wn = (wid >> 2) * 32;   // warp N offset (tokens)
    const int m_base = blockIdx.x * BLOCK_M;

    // ---- per-lane ldmatrix offsets ----
    const int a_row  = (lane & 7) + ((lane >> 3) & 1) * 8;
    const uint32_t a_byte = ((lane >> 4) & 1) * 16;
    const uint32_t a_rel0 = (uint32_t)(wm + a_row) * (PH * 2) + a_byte;
    const uint32_t a_rel1 = a_rel0 + 16 * (PH * 2);
    const int b_row  = (lane & 7) + ((lane >> 4) & 1) * 8;
    const uint32_t b_byte = ((lane >> 3) & 1) * 16;
    const uint32_t b_rel0 = (uint32_t)(wn + b_row) * (PH * 2) + b_byte;
    const uint32_t b_rel1 = b_rel0 + 16 * (PH * 2);

    // ---- W register staging: thread covers row=tid>>1, half=tid&1 (16 floats) ----
    const int wrow = tid >> 1;
    const int whalf = tid & 1;

    auto ldg_w = [&](int chunk, float4* r) {
        const float4* p;
        if (chunk < NCHUNK_MAIN) {
            p = (const float4*)(w + (size_t)(m_base + wrow) * IN_F
                                + chunk * KBLK + whalf * 16);
        } else {
            p = (const float4*)(lB + (size_t)(m_base + wrow) * RANK
                                + (chunk - NCHUNK_MAIN) * KBLK + whalf * 16);
        }
        r[0] = p[0]; r[1] = p[1]; r[2] = p[2]; r[3] = p[3];
    };

    __half* const wh_my = (__half*)(smem_c + OFF_WH) + wrow * PH + whalf * 16;
    auto sts_w = [&](const float4* r, int buf) {
        uint4 p0, p1;
        p0.x = h2u(__floats2half2_rn(r[0].x, r[0].y));
        p0.y = h2u(__floats2half2_rn(r[0].z, r[0].w));
        p0.z = h2u(__floats2half2_rn(r[1].x, r[1].y));
        p0.w = h2u(__floats2half2_rn(r[1].z, r[1].w));
        p1.x = h2u(__floats2half2_rn(r[2].x, r[2].y));
        p1.y = h2u(__floats2half2_rn(r[2].z, r[2].w));
        p1.z = h2u(__floats2half2_rn(r[3].x, r[3].y));
        p1.w = h2u(__floats2half2_rn(r[3].z, r[3].w));
        __half* dst = wh_my + buf * (WH_BYTES / 2);
        ((uint4*)dst)[0] = p0;
        ((uint4*)(dst + 8))[0] = p1;
    };

    // ---- X stage loader (cp.async, 1 op per thread) ----
    auto load_x = [&](int chunk, int slot) {
        const __half* b_base; int b_stride; int k0;
        if (chunk < NCHUNK_MAIN) {
            b_base = xh;  b_stride = IN_F; k0 = chunk * KBLK;
        } else {
            b_base = t2h; b_stride = RANK; k0 = (chunk - NCHUNK_MAIN) * KBLK;
        }
        uint32_t s_x = sb + OFF_XH + (uint32_t)slot * XH_STAGE_B;
        int row = tid >> 2, seg = tid & 3;
        cp16(s_x + (uint32_t)(row * PH + seg * 8) * 2,
             b_base + (size_t)row * b_stride + k0 + seg * 8);
    };

    // ---- prologue ----
    float4 rW0[4], rW1[4];
    ldg_w(0, rW0);
    ldg_w(1, rW1);
#pragma unroll
    for (int s = 0; s < XSTAGES - 1; ++s) {   // X stages 0,1,2 in flight
        load_x(s, s);
        CP_COMMIT();
    }
    sts_w(rW0, 0);          // Wh[0] <- chunk 0
    ldg_w(2, rW0);          // rW0 <- chunk 2
    CP_WAIT2();             // own X stage 0 done
    __syncthreads();        // publish Wh[0] + everyone's X stage 0

    float d[2][4][4];
#pragma unroll
    for (int mi = 0; mi < 2; ++mi)
#pragma unroll
        for (int ni = 0; ni < 4; ++ni)
#pragma unroll
            for (int r = 0; r < 4; ++r) d[mi][ni][r] = 0.f;

    // ---- mainloop (one barrier per iteration) ----
    // invariants entering iter it: Wh[it&1] holds chunk it (published);
    // rW[(it+1)&1] holds chunk it+1; Xh[it&3] visible.
    for (int it = 0; it < NCHUNK_TOT; ++it) {
        // convert chunk it+1 -> Wh[(it+1)&1]; refill that reg buffer with chunk it+3.
        // Write-after-read on Wh[(it+1)&1]: last read by MMA(it-1), one barrier ago. OK.
        if (it + 1 < NCHUNK_TOT) {
            if ((it + 1) & 1) { sts_w(rW1, 1); if (it + 3 < NCHUNK_TOT) ldg_w(it + 3, rW1); }
            else              { sts_w(rW0, 0); if (it + 3 < NCHUNK_TOT) ldg_w(it + 3, rW0); }
        }

        // X refill: stage it+3 into slot (it-1)&3 (last read at iter it-1, barrier ago).
        {
            int nc = it + XSTAGES - 1;
            if (nc < NCHUNK_TOT) load_x(nc, nc & (XSTAGES - 1));
            CP_COMMIT();
        }

        // MMA on chunk it from Wh[it&1] and Xh[it&3]
        const uint32_t wh_b = sb + OFF_WH + (uint32_t)(it & 1) * WH_BYTES;
        const uint32_t xb   = sb + OFF_XH + (uint32_t)(it & (XSTAGES - 1)) * XH_STAGE_B;
#pragma unroll
        for (int kk = 0; kk < 2; ++kk) {
            const uint32_t k2 = kk * 32;   // 16 halfs = 32B
            uint32_t a0[4], a1[4], bq0[4], bq1[4];
            ldsm4(a0,  wh_b + a_rel0 + k2);
            ldsm4(a1,  wh_b + a_rel1 + k2);
            ldsm4(bq0, xb + b_rel0 + k2);
            ldsm4(bq1, xb + b_rel1 + k2);
            mma_f16(d[0][0], a0, bq0[0], bq0[1]);
            mma_f16(d[0][1], a0, bq0[2], bq0[3]);
            mma_f16(d[0][2], a0, bq1[0], bq1[1]);
            mma_f16(d[0][3], a0, bq1[2], bq1[3]);
            mma_f16(d[1][0], a1, bq0[0], bq0[1]);
            mma_f16(d[1][1], a1, bq0[2], bq0[3]);
            mma_f16(d[1][2], a1, bq1[0], bq1[1]);
            mma_f16(d[1][3], a1, bq1[2], bq1[3]);
        }

        CP_WAIT2();        // own X groups for stages <= it+1 complete
        __syncthreads();   // publish Wh[(it+1)&1] + everyone's X stage it+1
    }

    // ---- epilogue: D[m][n] -> out[n][m] ----
#pragma unroll
    for (int mi = 0; mi < 2; ++mi) {
#pragma unroll
        for (int ni = 0; ni < 4; ++ni) {
            int m = m_base + wm + mi * 16 + g;
            int n = wn + ni * 8 + 2 * t;
            out[(size_t)n * OUT_F + m]           = d[mi][ni][0];
            out[(size_t)(n + 1) * OUT_F + m]     = d[mi][ni][1];
            out[(size_t)n * OUT_F + m + 8]       = d[mi][ni][2];
            out[(size_t)(n + 1) * OUT_F + m + 8] = d[mi][ni][3];
        }
    }
}

// ---------------- host launch ----------------
extern "C" void kernel_launch(void* const* d_in, const int* in_sizes, int n_in,
                              void* d_out, int out_size) {
    const float* x  = (const float*)d_in[0];   // [64, 4096]
    const float* w  = (const float*)d_in[1];   // [16384, 4096]
    const float* lA = (const float*)d_in[2];   // [64, 4096]
    const float* lB = (const float*)d_in[3];   // [16384, 64]
    float* out = (float*)d_out;                // [64, 16384]

    void* xh_ptr = nullptr;
    void* t2_ptr = nullptr;
    cudaGetSymbolAddress(&xh_ptr, g_xh);
    cudaGetSymbolAddress(&t2_ptr, g_t2h);

    x2h_kernel<<<(NTOK * IN_F / 4) / 256, 256>>>((const float4*)x, (uint2*)xh_ptr);
    lora_t_kernel<<<64, 256>>>(x, lA, (__half*)t2_ptr);

    static int smem_set = 0;
    if (!smem_set) {
        cudaFuncSetAttribute(lora_main_kernel,
                             cudaFuncAttributeMaxDynamicSharedMemorySize, SMEM_BYTES);
        smem_set = 1;
    }
    lora_main_kernel<<<OUT_F / BLOCK_M, 256, SMEM_BYTES>>>(
        (const __half*)xh_ptr, w, lB, (const __half*)t2_ptr, out);
}

// round 8
// speedup vs baseline: 1.1661x; 1.1661x over previous
#include <cuda_runtime.h>
#include <cuda_fp16.h>
#include <cstdint>

// ---------------- problem constants ----------------
#define IN_F   4096
#define OUT_F  16384
#define NTOK   64
#define RANK   64

#define BLOCK_M 128          // out-features per CTA
#define KBLK    32           // K elems per pipeline stage
#define STAGES  4
#define THREADS 512
#define NCHUNK_MAIN (IN_F / KBLK)             // 128
#define NCHUNK_TOT  (NCHUNK_MAIN + RANK/KBLK) // 130

// ---------------- SMEM layout ----------------
#define P32        36                          // fp32 row pitch (floats)
#define W32_STAGE_F (BLOCK_M * P32)            // 4608 floats
#define W32_STAGE_B (W32_STAGE_F * 4)          // 18432 B
#define OFF_W32    0
#define PH         40                          // fp16 row pitch (halfs)
#define OFF_WH     (STAGES * W32_STAGE_B)      // 73728 (single buffer)
#define WH_BYTES   (BLOCK_M * PH * 2)          // 10240
#define OFF_XH     (OFF_WH + WH_BYTES)         // 83968
#define XH_STAGE_B (NTOK * PH * 2)             // 5120
#define SMEM_BYTES (OFF_XH + STAGES * XH_STAGE_B)  // 104448

// device scratch
__device__ __align__(256) __half g_xh[NTOK * IN_F];   // x in fp16
__device__ __align__(256) __half g_t2h[NTOK * RANK];  // 2*(x@A^T) in fp16

// ---------------- PTX helpers ----------------
__device__ __forceinline__ uint32_t smem_u32(const void* p) {
    uint32_t a;
    asm("{ .reg .u64 t; cvta.to.shared.u64 t, %1; cvt.u32.u64 %0, t; }" : "=r"(a) : "l"(p));
    return a;
}
__device__ __forceinline__ void cp16(uint32_t dst, const void* src) {
    asm volatile("cp.async.cg.shared.global [%0], [%1], 16;" :: "r"(dst), "l"(src));
}
#define CP_COMMIT() asm volatile("cp.async.commit_group;" ::: "memory")
#define CP_WAIT2()  asm volatile("cp.async.wait_group 2;" ::: "memory")

__device__ __forceinline__ void ldsm4(uint32_t* r, uint32_t addr) {
    asm volatile("ldmatrix.sync.aligned.m8n8.x4.shared.b16 {%0,%1,%2,%3}, [%4];"
                 : "=r"(r[0]), "=r"(r[1]), "=r"(r[2]), "=r"(r[3]) : "r"(addr));
}
__device__ __forceinline__ void mma_f16(float* d, const uint32_t* a,
                                        uint32_t b0, uint32_t b1) {
    asm volatile(
        "mma.sync.aligned.m16n8k16.row.col.f32.f16.f16.f32 "
        "{%0,%1,%2,%3}, {%4,%5,%6,%7}, {%8,%9}, {%0,%1,%2,%3};"
        : "+f"(d[0]), "+f"(d[1]), "+f"(d[2]), "+f"(d[3])
        : "r"(a[0]), "r"(a[1]), "r"(a[2]), "r"(a[3]), "r"(b0), "r"(b1));
}
__device__ __forceinline__ uint32_t h2u(__half2 h) {
    return *reinterpret_cast<uint32_t*>(&h);
}

// ---------------- prep 1: x -> fp16 ----------------
__global__ void __launch_bounds__(256) x2h_kernel(const float4* __restrict__ x4,
                                                  uint2* __restrict__ xh2) {
    int i = blockIdx.x * 256 + threadIdx.x;
    float4 v = x4[i];
    uint2 o;
    o.x = h2u(__floats2half2_rn(v.x, v.y));
    o.y = h2u(__floats2half2_rn(v.z, v.w));
    xh2[i] = o;
}

// ---------------- prep 2: t2h = fp16( 2 * (x @ A^T) ) ----------------
__global__ void __launch_bounds__(256) lora_t_kernel(const float* __restrict__ x,
                                                     const float* __restrict__ A,
                                                     __half* __restrict__ t2) {
    __shared__ float red[256];
    int tid  = threadIdx.x;
    int pair = tid & 63;
    int i  = pair >> 3;
    int j  = pair & 7;
    int kg = tid >> 6;
    int gi = (blockIdx.x >> 3) * 8 + i;
    int gj = (blockIdx.x & 7) * 8 + j;

    const float4* xr = (const float4*)(x + (size_t)gi * IN_F);
    const float4* ar = (const float4*)(A + (size_t)gj * IN_F);
    float acc = 0.f;
    int k0 = kg * 256;
#pragma unroll 4
    for (int k = k0; k < k0 + 256; ++k) {
        float4 a = xr[k];
        float4 b = ar[k];
        acc += a.x * b.x + a.y * b.y + a.z * b.z + a.w * b.w;
    }
    red[tid] = acc;
    __syncthreads();
    if (kg == 0) {
        float s = red[pair] + red[pair + 64] + red[pair + 128] + red[pair + 192];
        t2[gi * RANK + gj] = __float2half_rn(2.0f * s);
    }
}

// ---------------- main fused GEMM ----------------
// 128 CTAs, 512 threads (16 warps: 8 along M x 2 along N, warp tile 16x32).
// R4-proven two-barrier schedule; doubled warps to cover HMMA/LDSM latency.
__global__ void __launch_bounds__(THREADS, 1) lora_main_kernel(
    const __half* __restrict__ xh,     // [64,4096] fp16
    const float*  __restrict__ w,      // [16384,4096] fp32
    const float*  __restrict__ lB,     // [16384,64] fp32
    const __half* __restrict__ t2h,    // [64,64] fp16 (incl. 2x scale)
    float* __restrict__ out)           // [64,16384]
{
    extern __shared__ __align__(16) char smem_c[];
    float* smem_f = (float*)smem_c;
    const uint32_t sb = smem_u32(smem_c);
    const int tid  = threadIdx.x;
    const int wid  = tid >> 5;
    const int lane = tid & 31;
    const int g = lane >> 2;
    const int t = lane & 3;
    const int wm = (wid & 7) * 16;    // warp M offset (8 warps along M)
    const int wn = (wid >> 3) * 32;   // warp N offset (2 warps along N)
    const int m_base = blockIdx.x * BLOCK_M;

    // ---- per-lane ldmatrix offsets ----
    // A (Wh): x4 matrices [m0-7/k0, m8-15/k0, m0-7/k8, m8-15/k8]
    const int a_row  = (lane & 7) + ((lane >> 3) & 1) * 8;
    const uint32_t a_byte = ((lane >> 4) & 1) * 16;
    const uint32_t a_rel = (uint32_t)(wm + a_row) * (PH * 2) + a_byte;
    // B (Xh): x4 matrices [n0-7/k0, n0-7/k8, n8-15/k0, n8-15/k8]
    const int b_row  = (lane & 7) + ((lane >> 4) & 1) * 8;
    const uint32_t b_byte = ((lane >> 3) & 1) * 16;
    const uint32_t b_rel0 = (uint32_t)(wn + b_row) * (PH * 2) + b_byte;
    const uint32_t b_rel1 = b_rel0 + 16 * (PH * 2);

    // ---- stage loader ----
    auto load_stage = [&](int chunk, int stage) {
        const float* a_base; int a_stride;
        const __half* b_base; int b_stride;
        int k0;
        if (chunk < NCHUNK_MAIN) {
            a_base = w + (size_t)m_base * IN_F;  a_stride = IN_F;
            b_base = xh;                         b_stride = IN_F;
            k0 = chunk * KBLK;
        } else {
            a_base = lB + (size_t)m_base * RANK; a_stride = RANK;
            b_base = t2h;                        b_stride = RANK;
            k0 = (chunk - NCHUNK_MAIN) * KBLK;
        }
        uint32_t s_w = sb + OFF_W32 + (uint32_t)stage * W32_STAGE_B;
        // W: 128 rows x 8 x 16B = 1024 ops / 512 thr = 2 each
#pragma unroll
        for (int i = 0; i < 2; ++i) {
            int idx = tid + i * THREADS;
            int row = idx >> 3, c = idx & 7;
            cp16(s_w + (uint32_t)(row * P32 + c * 4) * 4,
                 a_base + (size_t)row * a_stride + k0 + c * 4);
        }
        // Xh: 64 rows x 4 x 16B = 256 ops -> threads 0..255 do one
        if (tid < 256) {
            uint32_t s_x = sb + OFF_XH + (uint32_t)stage * XH_STAGE_B;
            int row = tid >> 2, seg = tid & 3;
            cp16(s_x + (uint32_t)(row * PH + seg * 8) * 2,
                 b_base + (size_t)row * b_stride + k0 + seg * 8);
        }
    };

    // ---- prologue ----
#pragma unroll
    for (int s = 0; s < STAGES - 1; ++s) {
        load_stage(s, s);
        CP_COMMIT();
    }

    float d[4][4];
#pragma unroll
    for (int ni = 0; ni < 4; ++ni)
#pragma unroll
        for (int r = 0; r < 4; ++r) d[ni][r] = 0.f;

    const int cvt_row = tid >> 2;      // 0..127
    const int cvt_seg = tid & 3;       // 8 floats each

    // ---- mainloop (R4 schedule: wait+bar, convert, refill+commit, bar, mma) ----
    for (int it = 0; it < NCHUNK_TOT; ++it) {
        const int s = it & (STAGES - 1);
        CP_WAIT2();
        __syncthreads();   // stage `it` visible to all; prior MMA reads of Wh done

        // convert W32[s] -> Wh (fp16), 8 floats per thread
        {
            const float* srcp = smem_f + s * W32_STAGE_F + cvt_row * P32 + cvt_seg * 8;
            float4 v0 = ((const float4*)srcp)[0];
            float4 v1 = ((const float4*)srcp)[1];
            uint4 p;
            p.x = h2u(__floats2half2_rn(v0.x, v0.y));
            p.y = h2u(__floats2half2_rn(v0.z, v0.w));
            p.z = h2u(__floats2half2_rn(v1.x, v1.y));
            p.w = h2u(__floats2half2_rn(v1.z, v1.w));
            __half* whp = (__half*)(smem_c + OFF_WH) + cvt_row * PH + cvt_seg * 8;
            ((uint4*)whp)[0] = p;
        }

        // refill stage it+3 into slot (it+3)&3 == (it-1)&3
        {
            int nc = it + STAGES - 1;
            if (nc < NCHUNK_TOT) load_stage(nc, nc & (STAGES - 1));
            CP_COMMIT();
        }
        __syncthreads();   // Wh published

        const uint32_t wh_b = sb + OFF_WH;
        const uint32_t xb   = sb + OFF_XH + (uint32_t)s * XH_STAGE_B;
#pragma unroll
        for (int kk = 0; kk < 2; ++kk) {
            const uint32_t k2 = kk * 32;   // 16 halfs = 32B
            uint32_t a[4], bq0[4], bq1[4];
            ldsm4(a,   wh_b + a_rel + k2);
            ldsm4(bq0, xb + b_rel0 + k2);
            ldsm4(bq1, xb + b_rel1 + k2);
            mma_f16(d[0], a, bq0[0], bq0[1]);
            mma_f16(d[1], a, bq0[2], bq0[3]);
            mma_f16(d[2], a, bq1[0], bq1[1]);
            mma_f16(d[3], a, bq1[2], bq1[3]);
        }
    }

    // ---- epilogue: D[m][n] -> out[n][m] ----
#pragma unroll
    for (int ni = 0; ni < 4; ++ni) {
        int m = m_base + wm + g;
        int n = wn + ni * 8 + 2 * t;
        out[(size_t)n * OUT_F + m]           = d[ni][0];
        out[(size_t)(n + 1) * OUT_F + m]     = d[ni][1];
        out[(size_t)n * OUT_F + m + 8]       = d[ni][2];
        out[(size_t)(n + 1) * OUT_F + m + 8] = d[ni][3];
    }
}

// ---------------- host launch ----------------
extern "C" void kernel_launch(void* const* d_in, const int* in_sizes, int n_in,
                              void* d_out, int out_size) {
    const float* x  = (const float*)d_in[0];   // [64, 4096]
    const float* w  = (const float*)d_in[1];   // [16384, 4096]
    const float* lA = (const float*)d_in[2];   // [64, 4096]
    const float* lB = (const float*)d_in[3];   // [16384, 64]
    float* out = (float*)d_out;                // [64, 16384]

    void* xh_ptr = nullptr;
    void* t2_ptr = nullptr;
    cudaGetSymbolAddress(&xh_ptr, g_xh);
    cudaGetSymbolAddress(&t2_ptr, g_t2h);

    x2h_kernel<<<(NTOK * IN_F / 4) / 256, 256>>>((const float4*)x, (uint2*)xh_ptr);
    lora_t_kernel<<<64, 256>>>(x, lA, (__half*)t2_ptr);

    static int smem_set = 0;
    if (!smem_set) {
        cudaFuncSetAttribute(lora_main_kernel,
                             cudaFuncAttributeMaxDynamicSharedMemorySize, SMEM_BYTES);
        smem_set = 1;
    }
    lora_main_kernel<<<OUT_F / BLOCK_M, THREADS, SMEM_BYTES>>>(
        (const __half*)xh_ptr, w, lB, (const __half*)t2_ptr, out);
}

// round 9
// speedup vs baseline: 1.1794x; 1.0114x over previous
#include <cuda_runtime.h>
#include <cuda_fp16.h>
#include <cstdint>

// ---------------- problem constants ----------------
#define IN_F   4096
#define OUT_F  16384
#define NTOK   64
#define RANK   64

#define BLOCK_M 128          // out-features per CTA
#define KBLK    32           // K elems per pipeline stage
#define STAGES  4
#define THREADS 512
#define NCHUNK_MAIN (IN_F / KBLK)             // 128
#define NCHUNK_TOT  (NCHUNK_MAIN + RANK/KBLK) // 130

// ---------------- SMEM layout ----------------
#define P32        36                          // fp32 row pitch (floats)
#define W32_STAGE_F (BLOCK_M * P32)            // 4608 floats
#define W32_STAGE_B (W32_STAGE_F * 4)          // 18432 B
#define OFF_W32    0
#define PH         40                          // fp16 row pitch (halfs)
#define OFF_WH     (STAGES * W32_STAGE_B)      // 73728 (single buffer)
#define WH_BYTES   (BLOCK_M * PH * 2)          // 10240
#define OFF_XH     (OFF_WH + WH_BYTES)         // 83968
#define XH_STAGE_B (NTOK * PH * 2)             // 5120
#define SMEM_BYTES (OFF_XH + STAGES * XH_STAGE_B)  // 104448

// device scratch
__device__ __align__(256) __half g_xh[NTOK * IN_F];   // x in fp16
__device__ __align__(256) __half g_t2h[NTOK * RANK];  // 2*(x@A^T) in fp16

// ---------------- PTX helpers ----------------
__device__ __forceinline__ uint32_t smem_u32(const void* p) {
    uint32_t a;
    asm("{ .reg .u64 t; cvta.to.shared.u64 t, %1; cvt.u32.u64 %0, t; }" : "=r"(a) : "l"(p));
    return a;
}
__device__ __forceinline__ void cp16(uint32_t dst, const void* src) {
    asm volatile("cp.async.cg.shared.global [%0], [%1], 16;" :: "r"(dst), "l"(src));
}
#define CP_COMMIT() asm volatile("cp.async.commit_group;" ::: "memory")
#define CP_WAIT2()  asm volatile("cp.async.wait_group 2;" ::: "memory")

__device__ __forceinline__ void ldsm4(uint32_t* r, uint32_t addr) {
    asm volatile("ldmatrix.sync.aligned.m8n8.x4.shared.b16 {%0,%1,%2,%3}, [%4];"
                 : "=r"(r[0]), "=r"(r[1]), "=r"(r[2]), "=r"(r[3]) : "r"(addr));
}
__device__ __forceinline__ void mma_f16(float* d, const uint32_t* a,
                                        uint32_t b0, uint32_t b1) {
    asm volatile(
        "mma.sync.aligned.m16n8k16.row.col.f32.f16.f16.f32 "
        "{%0,%1,%2,%3}, {%4,%5,%6,%7}, {%8,%9}, {%0,%1,%2,%3};"
        : "+f"(d[0]), "+f"(d[1]), "+f"(d[2]), "+f"(d[3])
        : "r"(a[0]), "r"(a[1]), "r"(a[2]), "r"(a[3]), "r"(b0), "r"(b1));
}
__device__ __forceinline__ uint32_t h2u(__half2 h) {
    return *reinterpret_cast<uint32_t*>(&h);
}

// ---------------- prep: x->fp16 (all 128 blocks) + t2h (blocks 0..63) ----------------
// grid 128 x 256 threads. One launch replaces the former two (saves ~4us launch latency
// AND makes kernel_launch = 2 launches/call so ncu -s 5 lands on the main kernel).
__global__ void __launch_bounds__(256) prep_kernel(const float* __restrict__ x,
                                                   const float* __restrict__ A,
                                                   uint2* __restrict__ xh2,
                                                   __half* __restrict__ t2) {
    const float4* x4 = (const float4*)x;
    int tid = threadIdx.x;
    // ---- x -> fp16: 64*4096 floats = 65536 float4; 128 blocks x 512 float4 ----
    int base = blockIdx.x * 512;
#pragma unroll
    for (int i = 0; i < 2; ++i) {
        int idx = base + tid + i * 256;
        float4 v = x4[idx];
        uint2 o;
        o.x = h2u(__floats2half2_rn(v.x, v.y));
        o.y = h2u(__floats2half2_rn(v.z, v.w));
        xh2[idx] = o;
    }
    // ---- t2 = fp16(2*(x@A^T)): blocks 0..63 ----
    if (blockIdx.x < 64) {
        __shared__ float red[256];
        int pair = tid & 63;
        int i  = pair >> 3;
        int j  = pair & 7;
        int kg = tid >> 6;
        int gi = ((int)blockIdx.x >> 3) * 8 + i;
        int gj = ((int)blockIdx.x & 7) * 8 + j;

        const float4* xr = (const float4*)(x + (size_t)gi * IN_F);
        const float4* ar = (const float4*)(A + (size_t)gj * IN_F);
        float acc = 0.f;
        int k0 = kg * 256;
#pragma unroll 4
        for (int k = k0; k < k0 + 256; ++k) {
            float4 a = xr[k];
            float4 b = ar[k];
            acc += a.x * b.x + a.y * b.y + a.z * b.z + a.w * b.w;
        }
        red[tid] = acc;
        __syncthreads();
        if (kg == 0) {
            float s = red[pair] + red[pair + 64] + red[pair + 128] + red[pair + 192];
            t2[gi * RANK + gj] = __float2half_rn(2.0f * s);
        }
    }
}

// ---------------- main fused GEMM ----------------
// 128 CTAs, 512 threads (16 warps: 8 along M x 2 along N, warp tile 16x32).
// R8 schedule unchanged (the proven non-regressing structure).
__global__ void __launch_bounds__(THREADS, 1) lora_main_kernel(
    const __half* __restrict__ xh,     // [64,4096] fp16
    const float*  __restrict__ w,      // [16384,4096] fp32
    const float*  __restrict__ lB,     // [16384,64] fp32
    const __half* __restrict__ t2h,    // [64,64] fp16 (incl. 2x scale)
    float* __restrict__ out)           // [64,16384]
{
    extern __shared__ __align__(16) char smem_c[];
    float* smem_f = (float*)smem_c;
    const uint32_t sb = smem_u32(smem_c);
    const int tid  = threadIdx.x;
    const int wid  = tid >> 5;
    const int lane = tid & 31;
    const int g = lane >> 2;
    const int t = lane & 3;
    const int wm = (wid & 7) * 16;    // warp M offset (8 warps along M)
    const int wn = (wid >> 3) * 32;   // warp N offset (2 warps along N)
    const int m_base = blockIdx.x * BLOCK_M;

    // ---- per-lane ldmatrix offsets ----
    const int a_row  = (lane & 7) + ((lane >> 3) & 1) * 8;
    const uint32_t a_byte = ((lane >> 4) & 1) * 16;
    const uint32_t a_rel = (uint32_t)(wm + a_row) * (PH * 2) + a_byte;
    const int b_row  = (lane & 7) + ((lane >> 4) & 1) * 8;
    const uint32_t b_byte = ((lane >> 3) & 1) * 16;
    const uint32_t b_rel0 = (uint32_t)(wn + b_row) * (PH * 2) + b_byte;
    const uint32_t b_rel1 = b_rel0 + 16 * (PH * 2);

    // ---- stage loader ----
    auto load_stage = [&](int chunk, int stage) {
        const float* a_base; int a_stride;
        const __half* b_base; int b_stride;
        int k0;
        if (chunk < NCHUNK_MAIN) {
            a_base = w + (size_t)m_base * IN_F;  a_stride = IN_F;
            b_base = xh;                         b_stride = IN_F;
            k0 = chunk * KBLK;
        } else {
            a_base = lB + (size_t)m_base * RANK; a_stride = RANK;
            b_base = t2h;                        b_stride = RANK;
            k0 = (chunk - NCHUNK_MAIN) * KBLK;
        }
        uint32_t s_w = sb + OFF_W32 + (uint32_t)stage * W32_STAGE_B;
#pragma unroll
        for (int i = 0; i < 2; ++i) {
            int idx = tid + i * THREADS;
            int row = idx >> 3, c = idx & 7;
            cp16(s_w + (uint32_t)(row * P32 + c * 4) * 4,
                 a_base + (size_t)row * a_stride + k0 + c * 4);
        }
        if (tid < 256) {
            uint32_t s_x = sb + OFF_XH + (uint32_t)stage * XH_STAGE_B;
            int row = tid >> 2, seg = tid & 3;
            cp16(s_x + (uint32_t)(row * PH + seg * 8) * 2,
                 b_base + (size_t)row * b_stride + k0 + seg * 8);
        }
    };

    // ---- prologue ----
#pragma unroll
    for (int s = 0; s < STAGES - 1; ++s) {
        load_stage(s, s);
        CP_COMMIT();
    }

    float d[4][4];
#pragma unroll
    for (int ni = 0; ni < 4; ++ni)
#pragma unroll
        for (int r = 0; r < 4; ++r) d[ni][r] = 0.f;

    const int cvt_row = tid >> 2;      // 0..127
    const int cvt_seg = tid & 3;       // 8 floats each

    // ---- mainloop ----
    for (int it = 0; it < NCHUNK_TOT; ++it) {
        const int s = it & (STAGES - 1);
        CP_WAIT2();
        __syncthreads();   // stage `it` visible to all; prior MMA reads of Wh done

        // convert W32[s] -> Wh (fp16), 8 floats per thread
        {
            const float* srcp = smem_f + s * W32_STAGE_F + cvt_row * P32 + cvt_seg * 8;
            float4 v0 = ((const float4*)srcp)[0];
            float4 v1 = ((const float4*)srcp)[1];
            uint4 p;
            p.x = h2u(__floats2half2_rn(v0.x, v0.y));
            p.y = h2u(__floats2half2_rn(v0.z, v0.w));
            p.z = h2u(__floats2half2_rn(v1.x, v1.y));
            p.w = h2u(__floats2half2_rn(v1.z, v1.w));
            __half* whp = (__half*)(smem_c + OFF_WH) + cvt_row * PH + cvt_seg * 8;
            ((uint4*)whp)[0] = p;
        }

        // refill stage it+3 into slot (it+3)&3 == (it-1)&3
        {
            int nc = it + STAGES - 1;
            if (nc < NCHUNK_TOT) load_stage(nc, nc & (STAGES - 1));
            CP_COMMIT();
        }
        __syncthreads();   // Wh published

        const uint32_t wh_b = sb + OFF_WH;
        const uint32_t xb   = sb + OFF_XH + (uint32_t)s * XH_STAGE_B;
#pragma unroll
        for (int kk = 0; kk < 2; ++kk) {
            const uint32_t k2 = kk * 32;   // 16 halfs = 32B
            uint32_t a[4], bq0[4], bq1[4];
            ldsm4(a,   wh_b + a_rel + k2);
            ldsm4(bq0, xb + b_rel0 + k2);
            ldsm4(bq1, xb + b_rel1 + k2);
            mma_f16(d[0], a, bq0[0], bq0[1]);
            mma_f16(d[1], a, bq0[2], bq0[3]);
            mma_f16(d[2], a, bq1[0], bq1[1]);
            mma_f16(d[3], a, bq1[2], bq1[3]);
        }
    }

    // ---- epilogue: D[m][n] -> out[n][m] ----
#pragma unroll
    for (int ni = 0; ni < 4; ++ni) {
        int m = m_base + wm + g;
        int n = wn + ni * 8 + 2 * t;
        out[(size_t)n * OUT_F + m]           = d[ni][0];
        out[(size_t)(n + 1) * OUT_F + m]     = d[ni][1];
        out[(size_t)n * OUT_F + m + 8]       = d[ni][2];
        out[(size_t)(n + 1) * OUT_F + m + 8] = d[ni][3];
    }
}

// ---------------- host launch ----------------
extern "C" void kernel_launch(void* const* d_in, const int* in_sizes, int n_in,
                              void* d_out, int out_size) {
    const float* x  = (const float*)d_in[0];   // [64, 4096]
    const float* w  = (const float*)d_in[1];   // [16384, 4096]
    const float* lA = (const float*)d_in[2];   // [64, 4096]
    const float* lB = (const float*)d_in[3];   // [16384, 64]
    float* out = (float*)d_out;                // [64, 16384]

    void* xh_ptr = nullptr;
    void* t2_ptr = nullptr;
    cudaGetSymbolAddress(&xh_ptr, g_xh);
    cudaGetSymbolAddress(&t2_ptr, g_t2h);

    prep_kernel<<<128, 256>>>(x, lA, (uint2*)xh_ptr, (__half*)t2_ptr);

    static int smem_set = 0;
    if (!smem_set) {
        cudaFuncSetAttribute(lora_main_kernel,
                             cudaFuncAttributeMaxDynamicSharedMemorySize, SMEM_BYTES);
        smem_set = 1;
    }
    lora_main_kernel<<<OUT_F / BLOCK_M, THREADS, SMEM_BYTES>>>(
        (const __half*)xh_ptr, w, lB, (const __half*)t2_ptr, out);
}

// round 10
// speedup vs baseline: 1.2375x; 1.0492x over previous
#include <cuda_runtime.h>
#include <cuda_fp16.h>
#include <cstdint>

// ---------------- problem constants ----------------
#define IN_F   4096
#define OUT_F  16384
#define NTOK   64
#define RANK   64

#define BLOCK_M 128          // out-features per CTA
#define KBLK    64           // K elems per pipeline stage
#define STAGES  3
#define THREADS 256
#define NCHUNK_MAIN (IN_F / KBLK)             // 64
#define NCHUNK_TOT  (NCHUNK_MAIN + 1)         // 65 (1 lora tail chunk, K=RANK=64)

// ---------------- SMEM layout ----------------
#define P32        68                          // fp32 row pitch (floats): 64 + 4 pad
#define W32_STAGE_F (BLOCK_M * P32)            // 8704 floats
#define W32_STAGE_B (W32_STAGE_F * 4)          // 34816 B
#define OFF_W32    0
#define PH         72                          // fp16 row pitch (halfs): 64 + 8 pad
#define OFF_WH     (STAGES * W32_STAGE_B)      // 104448 (single fp16 W buffer)
#define WH_BYTES   (BLOCK_M * PH * 2)          // 18432
#define OFF_XH     (OFF_WH + WH_BYTES)         // 122880
#define XH_STAGE_B (NTOK * PH * 2)             // 9216
#define SMEM_BYTES (OFF_XH + STAGES * XH_STAGE_B)  // 150528

// device scratch
__device__ __align__(256) __half g_xh[NTOK * IN_F];   // x in fp16
__device__ __align__(256) __half g_t2h[NTOK * RANK];  // 2*(x@A^T) in fp16

// ---------------- PTX helpers ----------------
__device__ __forceinline__ uint32_t smem_u32(const void* p) {
    uint32_t a;
    asm("{ .reg .u64 t; cvta.to.shared.u64 t, %1; cvt.u32.u64 %0, t; }" : "=r"(a) : "l"(p));
    return a;
}
__device__ __forceinline__ void cp16(uint32_t dst, const void* src) {
    asm volatile("cp.async.cg.shared.global [%0], [%1], 16;" :: "r"(dst), "l"(src));
}
#define CP_COMMIT() asm volatile("cp.async.commit_group;" ::: "memory")
#define CP_WAIT1()  asm volatile("cp.async.wait_group 1;" ::: "memory")

__device__ __forceinline__ void ldsm4(uint32_t* r, uint32_t addr) {
    asm volatile("ldmatrix.sync.aligned.m8n8.x4.shared.b16 {%0,%1,%2,%3}, [%4];"
                 : "=r"(r[0]), "=r"(r[1]), "=r"(r[2]), "=r"(r[3]) : "r"(addr));
}
__device__ __forceinline__ void mma_f16(float* d, const uint32_t* a,
                                        uint32_t b0, uint32_t b1) {
    asm volatile(
        "mma.sync.aligned.m16n8k16.row.col.f32.f16.f16.f32 "
        "{%0,%1,%2,%3}, {%4,%5,%6,%7}, {%8,%9}, {%0,%1,%2,%3};"
        : "+f"(d[0]), "+f"(d[1]), "+f"(d[2]), "+f"(d[3])
        : "r"(a[0]), "r"(a[1]), "r"(a[2]), "r"(a[3]), "r"(b0), "r"(b1));
}
__device__ __forceinline__ uint32_t h2u(__half2 h) {
    return *reinterpret_cast<uint32_t*>(&h);
}
__device__ __forceinline__ float dot4(float4 a, float4 b) {
    return a.x * b.x + a.y * b.y + a.z * b.z + a.w * b.w;
}

// ---------------- prep: x->fp16 (all 128 blocks) + t2h (blocks 0..63) ----------------
// t2 inner loop: 4 independent accumulators, unroll 8 -> 16 loads in flight (MLP fix).
__global__ void __launch_bounds__(256) prep_kernel(const float* __restrict__ x,
                                                   const float* __restrict__ A,
                                                   uint2* __restrict__ xh2,
                                                   __half* __restrict__ t2) {
    const float4* x4 = (const float4*)x;
    int tid = threadIdx.x;
    // ---- x -> fp16: 65536 float4 over 128 blocks ----
    int base = blockIdx.x * 512;
#pragma unroll
    for (int i = 0; i < 2; ++i) {
        int idx = base + tid + i * 256;
        float4 v = x4[idx];
        uint2 o;
        o.x = h2u(__floats2half2_rn(v.x, v.y));
        o.y = h2u(__floats2half2_rn(v.z, v.w));
        xh2[idx] = o;
    }
    // ---- t2 = fp16(2*(x@A^T)): blocks 0..63 ----
    if (blockIdx.x < 64) {
        __shared__ float red[256];
        int pair = tid & 63;
        int i  = pair >> 3;
        int j  = pair & 7;
        int kg = tid >> 6;
        int gi = ((int)blockIdx.x >> 3) * 8 + i;
        int gj = ((int)blockIdx.x & 7) * 8 + j;

        const float4* xr = (const float4*)(x + (size_t)gi * IN_F);
        const float4* ar = (const float4*)(A + (size_t)gj * IN_F);
        float a0 = 0.f, a1 = 0.f, a2 = 0.f, a3 = 0.f;
        int k0 = kg * 256;
        for (int k = k0; k < k0 + 256; k += 8) {
            float4 xa[8], aa[8];
#pragma unroll
            for (int u = 0; u < 8; ++u) { xa[u] = xr[k + u]; aa[u] = ar[k + u]; }
            a0 += dot4(xa[0], aa[0]); a1 += dot4(xa[1], aa[1]);
            a2 += dot4(xa[2], aa[2]); a3 += dot4(xa[3], aa[3]);
            a0 += dot4(xa[4], aa[4]); a1 += dot4(xa[5], aa[5]);
            a2 += dot4(xa[6], aa[6]); a3 += dot4(xa[7], aa[7]);
        }
        red[tid] = (a0 + a1) + (a2 + a3);
        __syncthreads();
        if (kg == 0) {
            float s = red[pair] + red[pair + 64] + red[pair + 128] + red[pair + 192];
            t2[gi * RANK + gj] = __float2half_rn(2.0f * s);
        }
    }
}

// ---------------- main fused GEMM ----------------
// 128 CTAs, 256 threads (8 warps: 4 along M x 2 along N), KBLK=64, 3-stage cp.async.
// R4-proven two-barrier schedule; half the iterations of R4/R9.
__global__ void __launch_bounds__(THREADS, 1) lora_main_kernel(
    const __half* __restrict__ xh,     // [64,4096] fp16
    const float*  __restrict__ w,      // [16384,4096] fp32
    const float*  __restrict__ lB,     // [16384,64] fp32
    const __half* __restrict__ t2h,    // [64,64] fp16 (incl. 2x scale)
    float* __restrict__ out)           // [64,16384]
{
    extern __shared__ __align__(16) char smem_c[];
    float* smem_f = (float*)smem_c;
    const uint32_t sb = smem_u32(smem_c);
    const int tid  = threadIdx.x;
    const int wid  = tid >> 5;
    const int lane = tid & 31;
    const int g = lane >> 2;
    const int t = lane & 3;
    const int wm = (wid & 3) * 32;    // warp M offset (4 warps along M)
    const int wn = (wid >> 2) * 32;   // warp N offset (2 warps along N)
    const int m_base = blockIdx.x * BLOCK_M;

    // ---- per-lane ldmatrix offsets (row pitch 144 B) ----
    const int a_row  = (lane & 7) + ((lane >> 3) & 1) * 8;
    const uint32_t a_byte = ((lane >> 4) & 1) * 16;
    const uint32_t a_rel0 = (uint32_t)(wm + a_row) * (PH * 2) + a_byte;
    const uint32_t a_rel1 = a_rel0 + 16 * (PH * 2);
    const int b_row  = (lane & 7) + ((lane >> 4) & 1) * 8;
    const uint32_t b_byte = ((lane >> 3) & 1) * 16;
    const uint32_t b_rel0 = (uint32_t)(wn + b_row) * (PH * 2) + b_byte;
    const uint32_t b_rel1 = b_rel0 + 16 * (PH * 2);

    // ---- stage loader: W 128x64 fp32 (8 cp/thread) + X 64x64 fp16 (2 cp/thread) ----
    auto load_stage = [&](int chunk, int stage) {
        const float* a_base; int a_stride;
        const __half* b_base; int b_stride;
        int k0;
        if (chunk < NCHUNK_MAIN) {
            a_base = w + (size_t)m_base * IN_F;  a_stride = IN_F;
            b_base = xh;                         b_stride = IN_F;
            k0 = chunk * KBLK;
        } else {
            a_base = lB + (size_t)m_base * RANK; a_stride = RANK;
            b_base = t2h;                        b_stride = RANK;
            k0 = 0;
        }
        uint32_t s_w = sb + OFF_W32 + (uint32_t)stage * W32_STAGE_B;
#pragma unroll
        for (int i = 0; i < 8; ++i) {
            int idx = tid + i * THREADS;
            int row = idx >> 4, c = idx & 15;
            cp16(s_w + (uint32_t)(row * P32 + c * 4) * 4,
                 a_base + (size_t)row * a_stride + k0 + c * 4);
        }
        uint32_t s_x = sb + OFF_XH + (uint32_t)stage * XH_STAGE_B;
#pragma unroll
        for (int i = 0; i < 2; ++i) {
            int idx = tid + i * THREADS;
            int row = idx >> 3, seg = idx & 7;
            cp16(s_x + (uint32_t)(row * PH + seg * 8) * 2,
                 b_base + (size_t)row * b_stride + k0 + seg * 8);
        }
    };

    // ---- convert: thread covers (row = tid&127, half = tid>>7) -> 32 floats ----
    // Bank-conflict-free: warp spans 32 consecutive rows (272B pitch = 4-bank shift/row).
    const int cvt_row  = tid & 127;
    const int cvt_half = tid >> 7;
    auto convert = [&](int slot) {
        const float* srcp = smem_f + slot * W32_STAGE_F + cvt_row * P32 + cvt_half * 32;
        __half* whp = (__half*)(smem_c + OFF_WH) + cvt_row * PH + cvt_half * 32;
#pragma unroll
        for (int q = 0; q < 2; ++q) {
            float4 v0 = ((const float4*)(srcp + q * 16))[0];
            float4 v1 = ((const float4*)(srcp + q * 16))[1];
            float4 v2 = ((const float4*)(srcp + q * 16))[2];
            float4 v3 = ((const float4*)(srcp + q * 16))[3];
            uint4 p0, p1;
            p0.x = h2u(__floats2half2_rn(v0.x, v0.y));
            p0.y = h2u(__floats2half2_rn(v0.z, v0.w));
            p0.z = h2u(__floats2half2_rn(v1.x, v1.y));
            p0.w = h2u(__floats2half2_rn(v1.z, v1.w));
            p1.x = h2u(__floats2half2_rn(v2.x, v2.y));
            p1.y = h2u(__floats2half2_rn(v2.z, v2.w));
            p1.z = h2u(__floats2half2_rn(v3.x, v3.y));
            p1.w = h2u(__floats2half2_rn(v3.z, v3.w));
            ((uint4*)(whp + q * 16))[0] = p0;
            ((uint4*)(whp + q * 16 + 8))[0] = p1;
        }
    };

    // ---- prologue: chunks 0,1 in flight ----
    load_stage(0, 0);
    CP_COMMIT();
    load_stage(1, 1);
    CP_COMMIT();

    float d[2][4][4];
#pragma unroll
    for (int mi = 0; mi < 2; ++mi)
#pragma unroll
        for (int ni = 0; ni < 4; ++ni)
#pragma unroll
            for (int r = 0; r < 4; ++r) d[mi][ni][r] = 0.f;

    // ---- mainloop: 65 iterations, 2 barriers each ----
    int s = 0;        // slot of chunk `it`
    int s2 = 2;       // slot for chunk `it+2`
    for (int it = 0; it < NCHUNK_TOT; ++it) {
        CP_WAIT1();
        __syncthreads();   // chunk `it` visible to ALL; prior MMA reads of Wh done

        convert(s);        // W32[s] -> Wh (fp16)

        {                  // refill chunk it+2 into slot s2 (retired slot of it-1)
            int nc = it + 2;
            if (nc < NCHUNK_TOT) load_stage(nc, s2);
            CP_COMMIT();
        }
        __syncthreads();   // Wh published

        const uint32_t wh_b = sb + OFF_WH;
        const uint32_t xb   = sb + OFF_XH + (uint32_t)s * XH_STAGE_B;
#pragma unroll
        for (int kk = 0; kk < 4; ++kk) {
            const uint32_t k2 = kk * 32;   // 16 halfs = 32B
            uint32_t a0[4], a1[4], bq0[4], bq1[4];
            ldsm4(a0,  wh_b + a_rel0 + k2);
            ldsm4(a1,  wh_b + a_rel1 + k2);
            ldsm4(bq0, xb + b_rel0 + k2);
            ldsm4(bq1, xb + b_rel1 + k2);
            mma_f16(d[0][0], a0, bq0[0], bq0[1]);
            mma_f16(d[0][1], a0, bq0[2], bq0[3]);
            mma_f16(d[0][2], a0, bq1[0], bq1[1]);
            mma_f16(d[0][3], a0, bq1[2], bq1[3]);
            mma_f16(d[1][0], a1, bq0[0], bq0[1]);
            mma_f16(d[1][1], a1, bq0[2], bq0[3]);
            mma_f16(d[1][2], a1, bq1[0], bq1[1]);
            mma_f16(d[1][3], a1, bq1[2], bq1[3]);
        }

        if (++s == STAGES) s = 0;
        if (++s2 == STAGES) s2 = 0;
    }

    // ---- epilogue: D[m][n] -> out[n][m] ----
#pragma unroll
    for (int mi = 0; mi < 2; ++mi) {
#pragma unroll
        for (int ni = 0; ni < 4; ++ni) {
            int m = m_base + wm + mi * 16 + g;
            int n = wn + ni * 8 + 2 * t;
            out[(size_t)n * OUT_F + m]           = d[mi][ni][0];
            out[(size_t)(n + 1) * OUT_F + m]     = d[mi][ni][1];
            out[(size_t)n * OUT_F + m + 8]       = d[mi][ni][2];
            out[(size_t)(n + 1) * OUT_F + m + 8] = d[mi][ni][3];
        }
    }
}

// ---------------- host launch ----------------
extern "C" void kernel_launch(void* const* d_in, const int* in_sizes, int n_in,
                              void* d_out, int out_size) {
    const float* x  = (const float*)d_in[0];   // [64, 4096]
    const float* w  = (const float*)d_in[1];   // [16384, 4096]
    const float* lA = (const float*)d_in[2];   // [64, 4096]
    const float* lB = (const float*)d_in[3];   // [16384, 64]
    float* out = (float*)d_out;                // [64, 16384]

    void* xh_ptr = nullptr;
    void* t2_ptr = nullptr;
    cudaGetSymbolAddress(&xh_ptr, g_xh);
    cudaGetSymbolAddress(&t2_ptr, g_t2h);

    prep_kernel<<<128, 256>>>(x, lA, (uint2*)xh_ptr, (__half*)t2_ptr);

    static int smem_set = 0;
    if (!smem_set) {
        cudaFuncSetAttribute(lora_main_kernel,
                             cudaFuncAttributeMaxDynamicSharedMemorySize, SMEM_BYTES);
        smem_set = 1;
    }
    lora_main_kernel<<<OUT_F / BLOCK_M, THREADS, SMEM_BYTES>>>(
        (const __half*)xh_ptr, w, lB, (const __half*)t2_ptr, out);
}

// round 11
// speedup vs baseline: 1.5683x; 1.2673x over previous
#include <cuda_runtime.h>
#include <cuda_fp16.h>
#include <cstdint>

// ---------------- problem constants ----------------
#define IN_F   4096
#define OUT_F  16384
#define NTOK   64
#define RANK   64

#define BLOCK_M 128          // out-features per CTA
#define KBLK    64           // K elems per pipeline stage
#define STAGES  4
#define THREADS 256
#define NCHUNK_MAIN (IN_F / KBLK)             // 64
#define NCHUNK_TOT  (NCHUNK_MAIN + 1)         // 65 (lora tail chunk)

// ---------------- main-kernel SMEM layout ----------------
#define P32        68                          // fp32 row pitch (floats)
#define W32_STAGE_F (BLOCK_M * P32)            // 8704 floats
#define W32_STAGE_B (W32_STAGE_F * 4)          // 34816 B
#define OFF_W32    0
#define PH         72                          // fp16 row pitch (halfs)
#define OFF_WH     (STAGES * W32_STAGE_B)      // 139264
#define WH_BYTES   (BLOCK_M * PH * 2)          // 18432
#define OFF_XH     (OFF_WH + WH_BYTES)         // 157696
#define XH_STAGE_B (NTOK * PH * 2)             // 9216
#define SMEM_BYTES (OFF_XH + STAGES * XH_STAGE_B)  // 194560

// device scratch
__device__ __align__(256) __half g_xh[NTOK * IN_F];    // x in fp16
__device__ __align__(256) __half g_t2h[NTOK * RANK];   // 2*(x@A^T) in fp16
__device__ __align__(256) float  g_part[64 * NTOK * RANK];  // K-slice partials

// ---------------- PTX helpers ----------------
__device__ __forceinline__ uint32_t smem_u32(const void* p) {
    uint32_t a;
    asm("{ .reg .u64 t; cvta.to.shared.u64 t, %1; cvt.u32.u64 %0, t; }" : "=r"(a) : "l"(p));
    return a;
}
__device__ __forceinline__ void cp16(uint32_t dst, const void* src) {
    asm volatile("cp.async.cg.shared.global [%0], [%1], 16;" :: "r"(dst), "l"(src));
}
#define CP_COMMIT() asm volatile("cp.async.commit_group;" ::: "memory")
#define CP_WAITG2() asm volatile("cp.async.wait_group 2;" ::: "memory")

__device__ __forceinline__ void ldsm4(uint32_t* r, uint32_t addr) {
    asm volatile("ldmatrix.sync.aligned.m8n8.x4.shared.b16 {%0,%1,%2,%3}, [%4];"
                 : "=r"(r[0]), "=r"(r[1]), "=r"(r[2]), "=r"(r[3]) : "r"(addr));
}
__device__ __forceinline__ void mma_f16(float* d, const uint32_t* a,
                                        uint32_t b0, uint32_t b1) {
    asm volatile(
        "mma.sync.aligned.m16n8k16.row.col.f32.f16.f16.f32 "
        "{%0,%1,%2,%3}, {%4,%5,%6,%7}, {%8,%9}, {%0,%1,%2,%3};"
        : "+f"(d[0]), "+f"(d[1]), "+f"(d[2]), "+f"(d[3])
        : "r"(a[0]), "r"(a[1]), "r"(a[2]), "r"(a[3]), "r"(b0), "r"(b1));
}
__device__ __forceinline__ uint32_t h2u(__half2 h) {
    return *reinterpret_cast<uint32_t*>(&h);
}
__device__ __forceinline__ float dot4(float4 a, float4 b) {
    return a.x * b.x + a.y * b.y + a.z * b.z + a.w * b.w;
}

// ---------------- prep A: x->fp16 (blocks 0..127) + t2 K-slice partials (128..191) ---
__global__ void __launch_bounds__(256) prep_kernel(const float* __restrict__ x,
                                                   const float* __restrict__ A,
                                                   uint2* __restrict__ xh2,
                                                   float* __restrict__ part) {
    int tid = threadIdx.x;
    if (blockIdx.x < 128) {
        // x -> fp16: 65536 float4 over 128 blocks
        const float4* x4 = (const float4*)x;
        int base = blockIdx.x * 512;
#pragma unroll
        for (int i = 0; i < 2; ++i) {
            int idx = base + tid + i * 256;
            float4 v = x4[idx];
            uint2 o;
            o.x = h2u(__floats2half2_rn(v.x, v.y));
            o.y = h2u(__floats2half2_rn(v.z, v.w));
            xh2[idx] = o;
        }
        return;
    }
    // ---- t2 partial for K-slice s: part[s][i][j] = sum_{k in slice} x[i,k]*A[j,k] ----
    int s = blockIdx.x - 128;                 // 0..63
    __shared__ float4 xs[64][17];             // 64 rows x 64 floats (pitch 17 f4)
    __shared__ float4 as[64][17];
    // load both tiles: 1024 f4 each, 4 per thread
#pragma unroll
    for (int i = 0; i < 4; ++i) {
        int idx = tid + i * 256;
        int row = idx >> 4, c = idx & 15;
        xs[row][c] = ((const float4*)x)[(size_t)row * (IN_F / 4) + s * 16 + c];
        as[row][c] = ((const float4*)A)[(size_t)row * (IN_F / 4) + s * 16 + c];
    }
    __syncthreads();
    // 16x16 threads, each computes a 4x4 pair tile
    int ti = tid >> 4, tj = tid & 15;
    float acc[4][4];
#pragma unroll
    for (int r = 0; r < 4; ++r)
#pragma unroll
        for (int c = 0; c < 4; ++c) acc[r][c] = 0.f;
#pragma unroll
    for (int kc = 0; kc < 16; ++kc) {
        float4 xv[4], av[4];
#pragma unroll
        for (int r = 0; r < 4; ++r) xv[r] = xs[ti * 4 + r][kc];
#pragma unroll
        for (int c = 0; c < 4; ++c) av[c] = as[tj * 4 + c][kc];
#pragma unroll
        for (int r = 0; r < 4; ++r)
#pragma unroll
            for (int c = 0; c < 4; ++c) acc[r][c] += dot4(xv[r], av[c]);
    }
    float* dst = part + (size_t)s * (NTOK * RANK);
#pragma unroll
    for (int r = 0; r < 4; ++r)
#pragma unroll
        for (int c = 0; c < 4; ++c)
            dst[(ti * 4 + r) * RANK + tj * 4 + c] = acc[r][c];
}

// ---------------- prep B: reduce 64 partials -> t2h = fp16(2*sum) ----------------
__global__ void __launch_bounds__(256) reduce_kernel(const float* __restrict__ part,
                                                     __half* __restrict__ t2) {
    int idx = blockIdx.x * 256 + threadIdx.x;     // 0..4095
    float s0 = 0.f, s1 = 0.f, s2 = 0.f, s3 = 0.f;
#pragma unroll
    for (int s = 0; s < 64; s += 4) {
        s0 += part[(size_t)s * 4096 + idx];
        s1 += part[(size_t)(s + 1) * 4096 + idx];
        s2 += part[(size_t)(s + 2) * 4096 + idx];
        s3 += part[(size_t)(s + 3) * 4096 + idx];
    }
    t2[idx] = __float2half_rn(2.0f * ((s0 + s1) + (s2 + s3)));
}

// ---------------- main fused GEMM ----------------
// 128 CTAs, 256 threads (8 warps: 4M x 2N), KBLK=64, 4-stage cp.async (wait depth 2).
__global__ void __launch_bounds__(THREADS, 1) lora_main_kernel(
    const __half* __restrict__ xh,     // [64,4096] fp16
    const float*  __restrict__ w,      // [16384,4096] fp32
    const float*  __restrict__ lB,     // [16384,64] fp32
    const __half* __restrict__ t2h,    // [64,64] fp16 (incl. 2x scale)
    float* __restrict__ out)           // [64,16384]
{
    extern __shared__ __align__(16) char smem_c[];
    float* smem_f = (float*)smem_c;
    const uint32_t sb = smem_u32(smem_c);
    const int tid  = threadIdx.x;
    const int wid  = tid >> 5;
    const int lane = tid & 31;
    const int g = lane >> 2;
    const int t = lane & 3;
    const int wm = (wid & 3) * 32;    // warp M offset
    const int wn = (wid >> 2) * 32;   // warp N offset (tokens)
    const int m_base = blockIdx.x * BLOCK_M;

    // ---- per-lane ldmatrix offsets ----
    const int a_row  = (lane & 7) + ((lane >> 3) & 1) * 8;
    const uint32_t a_byte = ((lane >> 4) & 1) * 16;
    const uint32_t a_rel0 = (uint32_t)(wm + a_row) * (PH * 2) + a_byte;
    const uint32_t a_rel1 = a_rel0 + 16 * (PH * 2);
    const int b_row  = (lane & 7) + ((lane >> 4) & 1) * 8;
    const uint32_t b_byte = ((lane >> 3) & 1) * 16;
    const uint32_t b_rel0 = (uint32_t)(wn + b_row) * (PH * 2) + b_byte;
    const uint32_t b_rel1 = b_rel0 + 16 * (PH * 2);

    // ---- stage loader: W 128x64 fp32 (8 cp/thread) + X 64x64 fp16 (2 cp/thread) ----
    auto load_stage = [&](int chunk, int stage) {
        const float* a_base; int a_stride;
        const __half* b_base; int b_stride;
        int k0;
        if (chunk < NCHUNK_MAIN) {
            a_base = w + (size_t)m_base * IN_F;  a_stride = IN_F;
            b_base = xh;                         b_stride = IN_F;
            k0 = chunk * KBLK;
        } else {
            a_base = lB + (size_t)m_base * RANK; a_stride = RANK;
            b_base = t2h;                        b_stride = RANK;
            k0 = 0;
        }
        uint32_t s_w = sb + OFF_W32 + (uint32_t)stage * W32_STAGE_B;
#pragma unroll
        for (int i = 0; i < 8; ++i) {
            int idx = tid + i * THREADS;
            int row = idx >> 4, c = idx & 15;
            cp16(s_w + (uint32_t)(row * P32 + c * 4) * 4,
                 a_base + (size_t)row * a_stride + k0 + c * 4);
        }
        uint32_t s_x = sb + OFF_XH + (uint32_t)stage * XH_STAGE_B;
#pragma unroll
        for (int i = 0; i < 2; ++i) {
            int idx = tid + i * THREADS;
            int row = idx >> 3, seg = idx & 7;
            cp16(s_x + (uint32_t)(row * PH + seg * 8) * 2,
                 b_base + (size_t)row * b_stride + k0 + seg * 8);
        }
    };

    // ---- convert: thread covers (row = tid&127, half = tid>>7) -> 32 floats ----
    const int cvt_row  = tid & 127;
    const int cvt_half = tid >> 7;
    auto convert = [&](int slot) {
        const float* srcp = smem_f + slot * W32_STAGE_F + cvt_row * P32 + cvt_half * 32;
        __half* whp = (__half*)(smem_c + OFF_WH) + cvt_row * PH + cvt_half * 32;
#pragma unroll
        for (int q = 0; q < 2; ++q) {
            float4 v0 = ((const float4*)(srcp + q * 16))[0];
            float4 v1 = ((const float4*)(srcp + q * 16))[1];
            float4 v2 = ((const float4*)(srcp + q * 16))[2];
            float4 v3 = ((const float4*)(srcp + q * 16))[3];
            uint4 p0, p1;
            p0.x = h2u(__floats2half2_rn(v0.x, v0.y));
            p0.y = h2u(__floats2half2_rn(v0.z, v0.w));
            p0.z = h2u(__floats2half2_rn(v1.x, v1.y));
            p0.w = h2u(__floats2half2_rn(v1.z, v1.w));
            p1.x = h2u(__floats2half2_rn(v2.x, v2.y));
            p1.y = h2u(__floats2half2_rn(v2.z, v2.w));
            p1.z = h2u(__floats2half2_rn(v3.x, v3.y));
            p1.w = h2u(__floats2half2_rn(v3.z, v3.w));
            ((uint4*)(whp + q * 16))[0] = p0;
            ((uint4*)(whp + q * 16 + 8))[0] = p1;
        }
    };

    // ---- prologue: chunks 0,1,2 in flight ----
    load_stage(0, 0); CP_COMMIT();
    load_stage(1, 1); CP_COMMIT();
    load_stage(2, 2); CP_COMMIT();

    float d[2][4][4];
#pragma unroll
    for (int mi = 0; mi < 2; ++mi)
#pragma unroll
        for (int ni = 0; ni < 4; ++ni)
#pragma unroll
            for (int r = 0; r < 4; ++r) d[mi][ni][r] = 0.f;

    // ---- mainloop: 65 iterations ----
    int s = 0;        // slot of chunk `it`
    for (int it = 0; it < NCHUNK_TOT; ++it) {
        CP_WAITG2();       // chunk `it` complete (own ops); it+1,it+2 may pend
        __syncthreads();   // chunk `it` visible to ALL; prior reads of slots done

        // refill chunk it+3 into slot (it+3)&3 FIRST (requests out before convert)
        {
            int nc = it + 3;
            if (nc < NCHUNK_TOT) load_stage(nc, nc & 3);
            CP_COMMIT();
        }

        convert(s);        // W32[s] -> Wh (fp16)
        __syncthreads();   // Wh published

        const uint32_t wh_b = sb + OFF_WH;
        const uint32_t xb   = sb + OFF_XH + (uint32_t)s * XH_STAGE_B;
#pragma unroll
        for (int kk = 0; kk < 4; ++kk) {
            const uint32_t k2 = kk * 32;   // 16 halfs = 32B
            uint32_t a0[4], a1[4], bq0[4], bq1[4];
            ldsm4(a0,  wh_b + a_rel0 + k2);
            ldsm4(a1,  wh_b + a_rel1 + k2);
            ldsm4(bq0, xb + b_rel0 + k2);
            ldsm4(bq1, xb + b_rel1 + k2);
            mma_f16(d[0][0], a0, bq0[0], bq0[1]);
            mma_f16(d[0][1], a0, bq0[2], bq0[3]);
            mma_f16(d[0][2], a0, bq1[0], bq1[1]);
            mma_f16(d[0][3], a0, bq1[2], bq1[3]);
            mma_f16(d[1][0], a1, bq0[0], bq0[1]);
            mma_f16(d[1][1], a1, bq0[2], bq0[3]);
            mma_f16(d[1][2], a1, bq1[0], bq1[1]);
            mma_f16(d[1][3], a1, bq1[2], bq1[3]);
        }

        s = (s + 1) & 3;
    }

    // ---- epilogue: D[m][n] -> out[n][m] ----
#pragma unroll
    for (int mi = 0; mi < 2; ++mi) {
#pragma unroll
        for (int ni = 0; ni < 4; ++ni) {
            int m = m_base + wm + mi * 16 + g;
            int n = wn + ni * 8 + 2 * t;
            out[(size_t)n * OUT_F + m]           = d[mi][ni][0];
            out[(size_t)(n + 1) * OUT_F + m]     = d[mi][ni][1];
            out[(size_t)n * OUT_F + m + 8]       = d[mi][ni][2];
            out[(size_t)(n + 1) * OUT_F + m + 8] = d[mi][ni][3];
        }
    }
}

// ---------------- host launch ----------------
extern "C" void kernel_launch(void* const* d_in, const int* in_sizes, int n_in,
                              void* d_out, int out_size) {
    const float* x  = (const float*)d_in[0];   // [64, 4096]
    const float* w  = (const float*)d_in[1];   // [16384, 4096]
    const float* lA = (const float*)d_in[2];   // [64, 4096]
    const float* lB = (const float*)d_in[3];   // [16384, 64]
    float* out = (float*)d_out;                // [64, 16384]

    void* xh_ptr = nullptr;
    void* t2_ptr = nullptr;
    void* part_ptr = nullptr;
    cudaGetSymbolAddress(&xh_ptr, g_xh);
    cudaGetSymbolAddress(&t2_ptr, g_t2h);
    cudaGetSymbolAddress(&part_ptr, g_part);

    prep_kernel<<<192, 256>>>(x, lA, (uint2*)xh_ptr, (float*)part_ptr);
    reduce_kernel<<<16, 256>>>((const float*)part_ptr, (__half*)t2_ptr);

    static int smem_set = 0;
    if (!smem_set) {
        cudaFuncSetAttribute(lora_main_kernel,
                             cudaFuncAttributeMaxDynamicSharedMemorySize, SMEM_BYTES);
        smem_set = 1;
    }
    lora_main_kernel<<<OUT_F / BLOCK_M, THREADS, SMEM_BYTES>>>(
        (const __half*)xh_ptr, w, lB, (const __half*)t2_ptr, out);
}